// round 15
// baseline (speedup 1.0000x reference)
#include <cuda_runtime.h>
#include <cuda_bf16.h>
#include <cstdint>

#define BSZ 32
#define LEN 8192
#define NPF 256          // output feature dim
#define INTMX 0x7fffffff

// ---------------------------------------------------------------------------
// Fused kernel. Grid (65, BSZ), 256 threads (8 warps). Block (b, u):
//   u < u0  : embedding for i in [start + u*128, +128). Warp w covers 16
//             i-positions; lane j handles float4 cols j and j+32 (feature
//             pairs 2j,2j+1 and 2j+64,2j+65).
//   u >= u0 : fill worker (u-u0) writes rows [(u-u0)*128, +128) of the
//             (0,1,0,1,...) prefix region [0, start) (whole row if no valid).
// Stores use DEFAULT eviction policy (not .cs): across graph replays a large
// subset of the output stays dirty-resident in the 126MB L2 and never drains
// to DRAM, reducing per-replay HBM traffic.
// ---------------------------------------------------------------------------
__global__ void __launch_bounds__(256) embed_kernel(const int* __restrict__ mask,
                                                    float* __restrict__ out) {
    const int b = blockIdx.y;
    const int u = blockIdx.x;          // 0..64
    const int tid = threadIdx.x;       // 0..255
    const int lane = tid & 31;
    const int w = tid >> 5;            // 0..7

    const int* __restrict__ mrow = mask + (size_t)b * LEN;

    __shared__ int s_start;
    __shared__ unsigned s_bits[16];

    // ---- Phase 1: first-valid index (warp 0, int4 ballot scan, 128/iter) --
    if (w == 0) {
        int res = INTMX;
        const int4* m4 = (const int4*)mrow;
        for (int k = 0; k < LEN / 128; ++k) {
            const int4 v = m4[k * 32 + lane];
            const unsigned bal = __ballot_sync(0xffffffffu, (v.x | v.y | v.z | v.w) != 0);
            if (bal) {
                const int fl = __ffs(bal) - 1;
                const int vx = __shfl_sync(0xffffffffu, v.x, fl);
                const int vy = __shfl_sync(0xffffffffu, v.y, fl);
                const int vz = __shfl_sync(0xffffffffu, v.z, fl);
                const int base = k * 128 + fl * 4;
                res = vx ? base : (vy ? base + 1 : (vz ? base + 2 : base + 3));
                break;
            }
        }
        if (lane == 0) s_start = res;
    }
    __syncthreads();

    const int raw = s_start;
    const int valid = (raw != INTMX);
    const int start = valid ? raw : 0;
    const int fill_end = valid ? start : LEN;
    const int u0 = valid ? ((LEN - start + 127) >> 7) : 0;

    // ---- fill workers ----
    if (u >= u0) {
        const int fa = (u - u0) * 128;
        if (fa >= fill_end) return;
        const int fb = min(fa + 128, fill_end);
        const float4 pat = make_float4(0.0f, 1.0f, 0.0f, 1.0f);
        float4* o = (float4*)(out + (size_t)(b * LEN + fa) * NPF);
        const int total = (fb - fa) * (NPF / 4);
        for (int t = tid; t < total; t += 256) o[t] = pat;
        return;
    }

    // ---- embedding block ----
    const int seg = u >> 2;                  // segment index (0..15)
    const int i0 = start + seg * 512;        // segment start (< LEN since u<u0)

    // segment window mask bits: 2 strips x 256 threads = 512 positions.
    // Warp w's ballot of strip s covers 32-chunk (s*8 + w) of the segment.
#pragma unroll
    for (int s = 0; s < 2; ++s) {
        const int pos = i0 + s * 256 + tid;
        const int v = (pos < LEN) ? mrow[pos] : 0;
        const unsigned bal = __ballot_sync(0xffffffffu, v != 0);
        if (lane == 0) s_bits[s * 8 + w] = bal;
    }
    __syncthreads();

    // this warp's 16-i range: chunk myc (32 wide), half hs (0 or 16)
    const int rel = (u & 3) * 128 + w * 16;  // offset within segment
    const int myc = rel >> 5;                // 0..15
    const int hs = rel & 16;                 // 0 or 16

    int m0 = 0, n = 0;
#pragma unroll
    for (int q = 0; q < 16; ++q) {
        const int p = __popc(s_bits[q]);
        n += p;
        if (q < myc) m0 += p;
    }
    const unsigned cb = s_bits[myc];
    m0 += __popc(cb & ((1u << hs) - 1u));    // hs==0 -> mask 0
    const unsigned bits = cb >> hs;

    const int iw = i0 + rel;                 // this warp's first i
    if (iw >= LEN) return;
    const int cnt = min(16, LEN - iw);

    const float base = 6.283185307179586f / ((float)n + 1e-6f);

    // deltas: lane j -> feature pairs (2j, 2j+1) and (2j+64, 2j+65)
    const float K2 = 0.10381025296523007f;   // log2(10000)/128
    const int j = lane;
    const float d0 = base * exp2f(-(float)(2 * j) * K2);
    const float d1 = base * exp2f(-(float)(2 * j + 1) * K2);
    const float d2 = d0 * 0.01f;             // 10000^(-64/128) = 1/100
    const float d3 = d1 * 0.01f;

    float s0, c0, s1, c1, s2, c2, s3, c3;
    float sd0, cd0, sd1, cd1, sd2, cd2, sd3, cd3;
    const float fm0 = (float)m0;             // m0*base <= 2*pi always
    __sincosf(fm0 * d0, &s0, &c0);
    __sincosf(fm0 * d1, &s1, &c1);
    __sincosf(fm0 * d2, &s2, &c2);
    __sincosf(fm0 * d3, &s3, &c3);
    __sincosf(d0, &sd0, &cd0);
    __sincosf(d1, &sd1, &cd1);
    __sincosf(d2, &sd2, &cd2);
    __sincosf(d3, &sd3, &cd3);

    float4* op0 = (float4*)(out + (size_t)(b * LEN + iw) * NPF) + j;
    float4* op1 = op0 + 32;

#define STEP(i)                                                               \
    do {                                                                      \
        if ((bits >> (i)) & 1u) {                                             \
            float t;                                                          \
            t = fmaf(s0, cd0, c0 * sd0); c0 = fmaf(c0, cd0, -s0 * sd0); s0 = t; \
            t = fmaf(s1, cd1, c1 * sd1); c1 = fmaf(c1, cd1, -s1 * sd1); s1 = t; \
            t = fmaf(s2, cd2, c2 * sd2); c2 = fmaf(c2, cd2, -s2 * sd2); s2 = t; \
            t = fmaf(s3, cd3, c3 * sd3); c3 = fmaf(c3, cd3, -s3 * sd3); s3 = t; \
        }                                                                     \
        *op0 = make_float4(s0, c0, s1, c1);                                   \
        *op1 = make_float4(s2, c2, s3, c3);                                   \
        op0 += NPF / 4; op1 += NPF / 4;                                       \
    } while (0)

    if (cnt == 16) {
#pragma unroll
        for (int i = 0; i < 16; ++i) STEP(i);
    } else {
        for (int i = 0; i < cnt; ++i) STEP(i);
    }
#undef STEP
}

extern "C" void kernel_launch(void* const* d_in, const int* in_sizes, int n_in,
                              void* d_out, int out_size) {
    (void)in_sizes; (void)n_in; (void)out_size;
    const int* mask = (const int*)d_in[1];   // inputs: x (unused), mask
    float* out = (float*)d_out;

    embed_kernel<<<dim3(65, BSZ), 256>>>(mask, out);
}

// round 16
// speedup vs baseline: 1.0569x; 1.0569x over previous
#include <cuda_runtime.h>
#include <cuda_bf16.h>
#include <cstdint>

#define BSZ 32
#define LEN 8192
#define NPF 256          // output feature dim
#define INTMX 0x7fffffff

// ---------------------------------------------------------------------------
// Fused kernel. Grid (65, BSZ), 256 threads (8 warps). Block (b, u):
//   u < u0  : embedding for i in [start + u*128, +128). Warp w covers 16
//             i-positions; lane j handles float4 cols j and j+32 (feature
//             pairs 2j,2j+1 and 2j+64,2j+65).
//   u >= u0 : fill worker (u-u0) writes rows [(u-u0)*128, +128) of the
//             (0,1,0,1,...) prefix region [0, start) (whole row when no
//             valid position exists).
// u0 = ceil((LEN-start)/128) <= 64; u0 + fill units <= 65 always.
//
// Math: within a segment, angle(i) = m(i) * delta_k where m is the segmented
// mask-count. Along i this is a conditional rotation by delta (4 FMAs) when
// mask==1 — replaces per-element sincos with FMA. Each warp reseeds exactly
// via __sincosf at its 16-i chunk start (drift <= 16 rotations ~ 1e-7).
// ---------------------------------------------------------------------------
__global__ void __launch_bounds__(256) embed_kernel(const int* __restrict__ mask,
                                                    float* __restrict__ out) {
    const int b = blockIdx.y;
    const int u = blockIdx.x;          // 0..64
    const int tid = threadIdx.x;       // 0..255
    const int lane = tid & 31;
    const int w = tid >> 5;            // 0..7

    const int* __restrict__ mrow = mask + (size_t)b * LEN;

    __shared__ int s_start;
    __shared__ unsigned s_bits[16];

    // ---- Phase 1: first-valid index (warp 0, int4 ballot scan, 128/iter) --
    if (w == 0) {
        int res = INTMX;
        const int4* m4 = (const int4*)mrow;
        for (int k = 0; k < LEN / 128; ++k) {
            const int4 v = m4[k * 32 + lane];
            const unsigned bal = __ballot_sync(0xffffffffu, (v.x | v.y | v.z | v.w) != 0);
            if (bal) {
                const int fl = __ffs(bal) - 1;
                const int vx = __shfl_sync(0xffffffffu, v.x, fl);
                const int vy = __shfl_sync(0xffffffffu, v.y, fl);
                const int vz = __shfl_sync(0xffffffffu, v.z, fl);
                const int base = k * 128 + fl * 4;
                res = vx ? base : (vy ? base + 1 : (vz ? base + 2 : base + 3));
                break;
            }
        }
        if (lane == 0) s_start = res;
    }
    __syncthreads();

    const int raw = s_start;
    const int valid = (raw != INTMX);
    const int start = valid ? raw : 0;
    const int fill_end = valid ? start : LEN;
    const int u0 = valid ? ((LEN - start + 127) >> 7) : 0;

    // ---- fill workers ----
    if (u >= u0) {
        const int fa = (u - u0) * 128;
        if (fa >= fill_end) return;
        const int fb = min(fa + 128, fill_end);
        const float4 pat = make_float4(0.0f, 1.0f, 0.0f, 1.0f);
        float4* o = (float4*)(out + (size_t)(b * LEN + fa) * NPF);
        const int total = (fb - fa) * (NPF / 4);
        for (int t = tid; t < total; t += 256) __stcs(o + t, pat);
        return;
    }

    // ---- embedding block ----
    const int seg = u >> 2;                  // segment index (0..15)
    const int i0 = start + seg * 512;        // segment start (< LEN since u<u0)

    // segment window mask bits: 2 strips x 256 threads = 512 positions.
    // Warp w's ballot of strip s covers 32-chunk (s*8 + w) of the segment.
#pragma unroll
    for (int s = 0; s < 2; ++s) {
        const int pos = i0 + s * 256 + tid;
        const int v = (pos < LEN) ? mrow[pos] : 0;
        const unsigned bal = __ballot_sync(0xffffffffu, v != 0);
        if (lane == 0) s_bits[s * 8 + w] = bal;
    }
    __syncthreads();

    // this warp's 16-i range: chunk myc (32 wide), half hs (0 or 16)
    const int rel = (u & 3) * 128 + w * 16;  // offset within segment
    const int myc = rel >> 5;                // 0..15
    const int hs = rel & 16;                 // 0 or 16

    int m0 = 0, n = 0;
#pragma unroll
    for (int q = 0; q < 16; ++q) {
        const int p = __popc(s_bits[q]);
        n += p;
        if (q < myc) m0 += p;
    }
    const unsigned cb = s_bits[myc];
    m0 += __popc(cb & ((1u << hs) - 1u));    // hs==0 -> mask 0
    const unsigned bits = cb >> hs;

    const int iw = i0 + rel;                 // this warp's first i
    if (iw >= LEN) return;
    const int cnt = min(16, LEN - iw);

    const float base = 6.283185307179586f / ((float)n + 1e-6f);

    // deltas: lane j -> feature pairs (2j, 2j+1) and (2j+64, 2j+65)
    const float K2 = 0.10381025296523007f;   // log2(10000)/128
    const int j = lane;
    const float d0 = base * exp2f(-(float)(2 * j) * K2);
    const float d1 = base * exp2f(-(float)(2 * j + 1) * K2);
    const float d2 = d0 * 0.01f;             // 10000^(-64/128) = 1/100
    const float d3 = d1 * 0.01f;

    float s0, c0, s1, c1, s2, c2, s3, c3;
    float sd0, cd0, sd1, cd1, sd2, cd2, sd3, cd3;
    const float fm0 = (float)m0;             // m0*base <= 2*pi always
    __sincosf(fm0 * d0, &s0, &c0);
    __sincosf(fm0 * d1, &s1, &c1);
    __sincosf(fm0 * d2, &s2, &c2);
    __sincosf(fm0 * d3, &s3, &c3);
    __sincosf(d0, &sd0, &cd0);
    __sincosf(d1, &sd1, &cd1);
    __sincosf(d2, &sd2, &cd2);
    __sincosf(d3, &sd3, &cd3);

    float4* op0 = (float4*)(out + (size_t)(b * LEN + iw) * NPF) + j;
    float4* op1 = op0 + 32;

#define STEP(i)                                                               \
    do {                                                                      \
        if ((bits >> (i)) & 1u) {                                             \
            float t;                                                          \
            t = fmaf(s0, cd0, c0 * sd0); c0 = fmaf(c0, cd0, -s0 * sd0); s0 = t; \
            t = fmaf(s1, cd1, c1 * sd1); c1 = fmaf(c1, cd1, -s1 * sd1); s1 = t; \
            t = fmaf(s2, cd2, c2 * sd2); c2 = fmaf(c2, cd2, -s2 * sd2); s2 = t; \
            t = fmaf(s3, cd3, c3 * sd3); c3 = fmaf(c3, cd3, -s3 * sd3); s3 = t; \
        }                                                                     \
        __stcs(op0, make_float4(s0, c0, s1, c1));                             \
        __stcs(op1, make_float4(s2, c2, s3, c3));                             \
        op0 += NPF / 4; op1 += NPF / 4;                                       \
    } while (0)

    if (cnt == 16) {
#pragma unroll
        for (int i = 0; i < 16; ++i) STEP(i);
    } else {
        for (int i = 0; i < cnt; ++i) STEP(i);
    }
#undef STEP
}

extern "C" void kernel_launch(void* const* d_in, const int* in_sizes, int n_in,
                              void* d_out, int out_size) {
    (void)in_sizes; (void)n_in; (void)out_size;
    const int* mask = (const int*)d_in[1];   // inputs: x (unused), mask
    float* out = (float*)d_out;

    embed_kernel<<<dim3(65, BSZ), 256>>>(mask, out);
}